// round 5
// baseline (speedup 1.0000x reference)
#include <cuda_runtime.h>
#include <cstdint>

// ---------------------------------------------------------------------------
// SINDy layer: out[b, c] = sum_t Theta(z[b])[t] * (Xi*mask)[t, c]
// B=65536, Z=32, terms = 1 + 32 + 528 + 5984 = 6545, out fp32 [65536, 32].
// Strategy: fp32 f32x2-packed FMA GEMV-per-row, Theta built on the fly,
// Xi_eff streamed through double-buffered SMEM via cp.async.
// ---------------------------------------------------------------------------

#define ZDIM 32
#define NT 6545
#define CHUNK 256
#define NCH 26                        // ceil(6545/256)
#define LASTC (NT - (NCH - 1) * CHUNK)  // 145
#define XI_BUF_BYTES (CHUNK * 128)    // 32768 per buffer
#define ROWS_PER_CTA 256
#define SMEM_BYTES (2 * XI_BUF_BYTES + ROWS_PER_CTA * ZDIM * 4)  // 98304

// Premasked Xi, row-major [NT][32]. __device__ global = legal scratch.
__device__ float g_xi_eff[NT * ZDIM];

// ---------------- PTX helpers ----------------
#define FMA2(d, a, b, c) \
    asm("fma.rn.f32x2 %0, %1, %2, %3;" : "=l"(d) : "l"(a), "l"(b), "l"(c))

#define PACK2(d, s) \
    asm("mov.b64 %0, {%1, %1};" : "=l"(d) : "r"(s))

#define UNPACK2(x, y, p) \
    asm("mov.b64 {%0, %1}, %2;" : "=f"(x), "=f"(y) : "l"(p))

#define LDSV2(a, b, addr) \
    asm volatile("ld.shared.v2.b64 {%0, %1}, [%2];" : "=l"(a), "=l"(b) : "r"(addr))

#define CP_ASYNC16(dst_u32, src_ptr) \
    asm volatile("cp.async.cg.shared.global [%0], [%1], 16;" \
                 :: "r"(dst_u32), "l"(src_ptr) : "memory")
#define CP_COMMIT() asm volatile("cp.async.commit_group;" ::: "memory")
#define CP_WAIT(N)  asm volatile("cp.async.wait_group %0;" :: "n"(N) : "memory")

// Stage one 256-term (32 KB) Xi chunk into SMEM buffer (c&1).
#define STAGE(c) do {                                                        \
    uint32_t _dst = sbase + (((c) & 1) ? (uint32_t)XI_BUF_BYTES : 0u);       \
    int _b4 = (c) * (CHUNK * 8);   /* float4 index of chunk start */         \
    const float4* _src = (const float4*)g_xi_eff;                            \
    _Pragma("unroll")                                                        \
    for (int _u = 0; _u < 16; _u++) {                                        \
        int _q = _u * 128 + tid;                                             \
        int _g = _b4 + _q;                                                   \
        if (_g < NT * 8) {                                                   \
            CP_ASYNC16(_dst + 16u * (uint32_t)_q, _src + _g);                \
        }                                                                    \
    }                                                                        \
    CP_COMMIT();                                                             \
} while (0)

// One polynomial term: 32 fp32 Xi values (broadcast from SMEM) FMA'd into the
// two rows' 16 packed accumulators each, then advance the Xi stream (with a
// uniform chunk-swap branch when a 256-term SMEM chunk is exhausted).
#define XI_TERM(th0, th1) do {                                               \
    unsigned long long _xv[16];                                              \
    _Pragma("unroll")                                                        \
    for (int _u = 0; _u < 8; _u++) {                                         \
        LDSV2(_xv[2 * _u], _xv[2 * _u + 1], xi_addr + 16u * _u);             \
    }                                                                        \
    unsigned long long _t0, _t1;                                             \
    PACK2(_t0, __float_as_uint(th0));                                        \
    PACK2(_t1, __float_as_uint(th1));                                        \
    _Pragma("unroll")                                                        \
    for (int _m = 0; _m < 16; _m++) {                                        \
        FMA2(acc0[_m], _t0, _xv[_m], acc0[_m]);                              \
        FMA2(acc1[_m], _t1, _xv[_m], acc1[_m]);                              \
    }                                                                        \
    if (--rem == 0) {          /* uniform across block */                    \
        __syncthreads();                                                     \
        ++ch;                                                                \
        if (ch + 1 < NCH) { STAGE(ch + 1); CP_WAIT(1); }                     \
        else              { CP_WAIT(0); }                                    \
        __syncthreads();                                                     \
        xi_addr = sbase + ((ch & 1) ? (uint32_t)XI_BUF_BYTES : 0u);          \
        rem = (ch == NCH - 1) ? LASTC : CHUNK;                               \
    } else {                                                                 \
        xi_addr += 128u;                                                     \
    }                                                                        \
} while (0)

// ---------------- prep: Xi_eff = Xi * Xi_mask ----------------
__global__ void prep_kernel(const float* __restrict__ Xi,
                            const float* __restrict__ mask) {
    int i = blockIdx.x * blockDim.x + threadIdx.x;
    if (i < NT * ZDIM) g_xi_eff[i] = Xi[i] * mask[i];
}

// ---------------- main kernel ----------------
__global__ void __launch_bounds__(128, 2)
sindy_kernel(const float* __restrict__ z, float* __restrict__ out) {
    extern __shared__ char smem[];
    const int tid = threadIdx.x;
    const int cta = blockIdx.x;
    const uint32_t sbase = (uint32_t)__cvta_generic_to_shared(smem);
    float* zsm = (float*)(smem + 2 * XI_BUF_BYTES);  // [k][r][lane] = [(k*2+r)*128 + lane]

    // Kick off Xi chunk prefetches first (overlap with z staging).
    STAGE(0);
    STAGE(1);

    // Stage z rows [cta*256, cta*256+256) transposed into SMEM.
    {
        const float4* zg = (const float4*)z + (size_t)cta * ROWS_PER_CTA * (ZDIM / 4);
        #pragma unroll
        for (int u = 0; u < 16; u++) {
            int q = u * 128 + tid;        // 0..2047 float4s
            float4 v = zg[q];
            int row = q >> 3;             // 0..255
            int k4  = q & 7;
            int r    = row >> 7;
            int lane = row & 127;
            zsm[(((k4 * 4 + 0) * 2 + r) << 7) + lane] = v.x;
            zsm[(((k4 * 4 + 1) * 2 + r) << 7) + lane] = v.y;
            zsm[(((k4 * 4 + 2) * 2 + r) << 7) + lane] = v.z;
            zsm[(((k4 * 4 + 3) * 2 + r) << 7) + lane] = v.w;
        }
    }

    CP_WAIT(1);        // chunk 0 resident
    __syncthreads();   // z + chunk0 visible to all

    unsigned long long acc0[16], acc1[16];
    #pragma unroll
    for (int m = 0; m < 16; m++) { acc0[m] = 0ull; acc1[m] = 0ull; }

    uint32_t xi_addr = sbase;
    int rem = CHUNK;
    int ch = 0;

    const float* zp = zsm + tid;   // zs(k,r) = zp[k*256 + r*128]

    // ---- term stream, exactly matching Xi row order ----
    // bias
    XI_TERM(1.0f, 1.0f);
    // linear: k = 0..31
    #pragma unroll 1
    for (int k = 0; k < ZDIM; k++) {
        XI_TERM(zp[k * 256], zp[k * 256 + 128]);
    }
    // quadratic: i <= j  (theta = z_i * z_j)
    #pragma unroll 1
    for (int i = 0; i < ZDIM; i++) {
        float a0 = zp[i * 256], a1 = zp[i * 256 + 128];
        #pragma unroll 1
        for (int k = i; k < ZDIM; k++) {
            XI_TERM(a0 * zp[k * 256], a1 * zp[k * 256 + 128]);
        }
    }
    // cubic: i <= j <= k  (theta = z_i * z_j * z_k, pair product hoisted)
    #pragma unroll 1
    for (int i = 0; i < ZDIM; i++) {
        float a0 = zp[i * 256], a1 = zp[i * 256 + 128];
        #pragma unroll 1
        for (int j = i; j < ZDIM; j++) {
            float p0 = a0 * zp[j * 256], p1 = a1 * zp[j * 256 + 128];
            #pragma unroll 1
            for (int k = j; k < ZDIM; k++) {
                XI_TERM(p0 * zp[k * 256], p1 * zp[k * 256 + 128]);
            }
        }
    }

    // ---- epilogue: write both rows ----
    size_t row0 = (size_t)cta * ROWS_PER_CTA + tid;
    float4* o0 = (float4*)(out + row0 * ZDIM);
    float4* o1 = (float4*)(out + (row0 + 128) * ZDIM);
    #pragma unroll
    for (int q = 0; q < 8; q++) {
        float4 v;
        UNPACK2(v.x, v.y, acc0[2 * q]);
        UNPACK2(v.z, v.w, acc0[2 * q + 1]);
        o0[q] = v;
    }
    #pragma unroll
    for (int q = 0; q < 8; q++) {
        float4 v;
        UNPACK2(v.x, v.y, acc1[2 * q]);
        UNPACK2(v.z, v.w, acc1[2 * q + 1]);
        o1[q] = v;
    }
}

// ---------------- launch ----------------
extern "C" void kernel_launch(void* const* d_in, const int* in_sizes, int n_in,
                              void* d_out, int out_size) {
    (void)in_sizes; (void)n_in; (void)out_size;
    const float* z    = (const float*)d_in[0];  // [65536, 32]
    const float* Xi   = (const float*)d_in[1];  // [6545, 32]
    const float* mask = (const float*)d_in[2];  // [6545, 32]
    // d_in[3] (z_mean) and d_in[4] (z_std) are unused by the reference.
    float* out = (float*)d_out;                 // [65536, 32]

    prep_kernel<<<(NT * ZDIM + 255) / 256, 256>>>(Xi, mask);

    (void)cudaFuncSetAttribute(sindy_kernel,
                               cudaFuncAttributeMaxDynamicSharedMemorySize,
                               SMEM_BYTES);
    sindy_kernel<<<65536 / ROWS_PER_CTA, 128, SMEM_BYTES>>>(z, out);
}